// round 17
// baseline (speedup 1.0000x reference)
#include <cuda_runtime.h>
#include <cuda_bf16.h>

#define N_NODES 100000
#define N_EDGES 1000000
#define DF 64
#define NC 16
#define CAP 32                       // slots per node; P(deg>32 | Poisson(10)) ~ 2e-9
#define OVF_CAP 32768

// ---------------- device scratch (no allocations allowed) ----------------
__device__ int   g_degi[N_NODES];                // true in-degree (counter)
__device__ float g_dinv[N_NODES];                // rsqrt(deg+1), precomputed
__device__ int   g_slot[(size_t)N_NODES * CAP];  // first CAP sources per node
__device__ float g_wslot[(size_t)N_NODES * CAP]; // dinv[src] cache (agg1 -> agg2)
__device__ int2  g_ovf[OVF_CAP];                 // overflow edges (dst, src)
__device__ int   g_ovf_cnt;
__device__ float g_h1[(size_t)N_NODES * DF];     // X @ W1 (fp32)
__device__ float g_h2[(size_t)N_NODES * NC];     // relu(agg1) @ W2
__device__ int   g_idx64;

// ---------------- side stream + events (host objects, created once) -------
static cudaStream_t g_s2 = nullptr;
static cudaEvent_t  g_ev_fork = nullptr, g_ev_join = nullptr;
static struct _StreamInit {
    _StreamInit() {
        cudaStreamCreateWithFlags(&g_s2, cudaStreamNonBlocking);
        cudaEventCreateWithFlags(&g_ev_fork, cudaEventDisableTiming);
        cudaEventCreateWithFlags(&g_ev_join, cudaEventDisableTiming);
    }
} _stream_init;

// ---------------- packed f32x2 helpers -------------------------------------
__device__ __forceinline__ unsigned long long fma_f32x2(unsigned long long a,
                                                        unsigned long long b,
                                                        unsigned long long c) {
    unsigned long long d;
    asm("fma.rn.f32x2 %0, %1, %2, %3;" : "=l"(d) : "l"(a), "l"(b), "l"(c));
    return d;
}
__device__ __forceinline__ unsigned long long dup_f32x2(float v) {
    unsigned long long d;
    asm("mov.b64 %0, {%1, %1};" : "=l"(d) : "f"(v));
    return d;
}

// row pointers via 32-bit byte offsets (buffers < 4GB)
__device__ __forceinline__ const float4* h1_row(const float4* base, int src, int c) {
    return (const float4*)((const char*)base + (((unsigned)src) << 8)) + c;
}
__device__ __forceinline__ const float* h2_row(const float* base, int src, int c) {
    return (const float*)((const char*)base + (((unsigned)src) << 6)) + c;
}

// ---------------- k1: zero counters + detect index width -------------------
__global__ void zero_detect_kernel(const int* __restrict__ e32) {
    int i = blockIdx.x * blockDim.x + threadIdx.x;
    if (i < N_NODES) g_degi[i] = 0;
    if (blockIdx.x == 0) {
        __shared__ int any_nz;
        if (threadIdx.x == 0) { any_nz = 0; g_ovf_cnt = 0; }
        __syncthreads();
        int nz = 0;
        for (int j = threadIdx.x; j < 4096; j += blockDim.x)
            if (e32[2 * j + 1] != 0) nz = 1;
        if (nz) any_nz = 1;
        __syncthreads();
        if (threadIdx.x == 0) g_idx64 = (any_nz == 0) ? 1 : 0;
    }
}

// ---------------- k2: one-pass slot scatter (count + adjacency) ------------
__global__ void slot_scatter_kernel(const void* __restrict__ edges) {
    int e = blockIdx.x * blockDim.x + threadIdx.x;
    if (e >= N_EDGES) return;
    const int* e32 = (const int*)edges;
    int s, d;
    if (g_idx64) {                    // low 32-bit word only (LE int64)
        s = e32[2 * e];
        d = e32[2 * (N_EDGES + e)];
    } else {
        s = e32[e];
        d = e32[N_EDGES + e];
    }
    int pos = atomicAdd(&g_degi[d], 1);
    if (pos < CAP) {
        g_slot[(size_t)d * CAP + pos] = s;
    } else {
        int o = atomicAdd(&g_ovf_cnt, 1);
        if (o < OVF_CAP) g_ovf[o] = make_int2(d, s);
    }
}

// ---------------- k3: dinv = rsqrt(deg + 1) --------------------------------
__global__ void dinv_kernel() {
    int i = blockIdx.x * blockDim.x + threadIdx.x;
    if (i < N_NODES) g_dinv[i] = rsqrtf((float)g_degi[i] + 1.0f);
}

// ------- GEMM1: h1 = X @ W1 (64 nodes/block, f32x2, 33KB smem) ------------
__global__ __launch_bounds__(256) void gemm1_kernel(const float* __restrict__ X,
                                                    const float* __restrict__ W1) {
    __shared__ float  xs[64][65];
    __shared__ float2 wst[32][65];
    int tid = threadIdx.x;
    int base = blockIdx.x * 64;
    for (int i = tid; i < 64 * 32; i += 256) {
        int k = i >> 5, p = i & 31;
        wst[p][k] = ((const float2*)W1)[i];      // (W1[k][2p], W1[k][2p+1])
    }
    for (int i = tid; i < 64 * 64; i += 256) {
        int n = i >> 6, k = i & 63;
        int node = base + n;
        xs[n][k] = (node < N_NODES) ? X[(size_t)node * 64 + k] : 0.0f;
    }
    __syncthreads();

    int node_t = tid >> 4;   // 0..15 -> 4 nodes each
    int col_t  = tid & 15;   // 0..15 -> col pairs col_t, col_t+16
    unsigned long long acc[4][2] = {};
#pragma unroll 8
    for (int k = 0; k < 64; k++) {
        unsigned long long wv0 = *(const unsigned long long*)&wst[col_t][k];
        unsigned long long wv1 = *(const unsigned long long*)&wst[col_t + 16][k];
#pragma unroll
        for (int i = 0; i < 4; i++) {
            unsigned long long xv = dup_f32x2(xs[node_t * 4 + i][k]);
            acc[i][0] = fma_f32x2(xv, wv0, acc[i][0]);
            acc[i][1] = fma_f32x2(xv, wv1, acc[i][1]);
        }
    }
#pragma unroll
    for (int i = 0; i < 4; i++) {
        int node = base + node_t * 4 + i;
        if (node < N_NODES) {
            float2* out = (float2*)(g_h1 + (size_t)node * 64);
            out[col_t]      = *(const float2*)&acc[i][0];
            out[col_t + 16] = *(const float2*)&acc[i][1];
        }
    }
}

// ------- agg1 + gemm2 fused: 2 nodes/warp, dinv-staged, w cached -----------
__global__ __launch_bounds__(256) void agg1_gemm2_kernel(const float* __restrict__ b1,
                                                         const float* __restrict__ W2) {
    __shared__ float w2s[64][17];    // [k][c], padded
    __shared__ float x1s[16][65];    // per-node x1 row, padded
    __shared__ int2  est[8][2][16];  // per warp-half (src, bits(dinv[src]))
    int tid = threadIdx.x;
    for (int i = tid; i < 64 * 16; i += 256) w2s[i >> 4][i & 15] = W2[i];
    __syncthreads();

    int wy   = tid >> 5;             // warp 0..7
    int lane = tid & 31;
    int half = lane >> 4;            // 0/1 -> own node
    int c    = lane & 15;            // 0..15 -> cols 4c..4c+3
    unsigned hmask = half ? 0xFFFF0000u : 0x0000FFFFu;
    int node = blockIdx.x * 16 + wy * 2 + half;
    bool active = (node < N_NODES);

    const float4* h1 = (const float4*)g_h1;
    float di = 0.0f;
    float4 acc = make_float4(0.f, 0.f, 0.f, 0.f);
    int cnt = 0, cnt32 = 0;
    if (active) {
        cnt = g_degi[node];
        cnt32 = min(cnt, CAP);
        di = g_dinv[node];
        acc = *h1_row(h1, node, c);
        acc.x *= di; acc.y *= di; acc.z *= di; acc.w *= di;   // self loop
    }
    const int* slotp = g_slot + (size_t)node * CAP;
    float* wslotp = g_wslot + (size_t)node * CAP;

    for (int bb = 0; bb < cnt32; bb += 16) {
        if (bb + c < cnt32) {
            int s = slotp[bb + c];
            float w = __ldg(&g_dinv[s]);
            wslotp[bb + c] = w;                   // cache for agg2 (coalesced)
            est[wy][half][c] = make_int2(s, __float_as_int(w));
        }
        __syncwarp(hmask);
        int m = min(cnt32 - bb, 16);
        for (int j = 0; j < m; j++) {
            int2 e = est[wy][half][j];           // LDS.64 broadcast
            float w = __int_as_float(e.y);
            float4 v = *h1_row(h1, e.x, c);      // LDG.128
            acc.x = fmaf(v.x, w, acc.x);
            acc.y = fmaf(v.y, w, acc.y);
            acc.z = fmaf(v.z, w, acc.z);
            acc.w = fmaf(v.w, w, acc.w);
        }
        __syncwarp(hmask);
    }
    if (cnt > CAP) {                              // overflow (expected: never)
        int no = min(g_ovf_cnt, OVF_CAP);
        for (int o = 0; o < no; o++) {
            int2 ev = g_ovf[o];
            if (ev.x == node) {
                float w = __ldg(&g_dinv[ev.y]);
                float4 v = *h1_row(h1, ev.y, c);
                acc.x = fmaf(v.x, w, acc.x); acc.y = fmaf(v.y, w, acc.y);
                acc.z = fmaf(v.z, w, acc.z); acc.w = fmaf(v.w, w, acc.w);
            }
        }
    }

    int nidx = wy * 2 + half;
    if (active) {
        float4 bb4 = ((const float4*)b1)[c];
        x1s[nidx][4 * c]     = fmaxf(fmaf(acc.x, di, bb4.x), 0.0f);
        x1s[nidx][4 * c + 1] = fmaxf(fmaf(acc.y, di, bb4.y), 0.0f);
        x1s[nidx][4 * c + 2] = fmaxf(fmaf(acc.z, di, bb4.z), 0.0f);
        x1s[nidx][4 * c + 3] = fmaxf(fmaf(acc.w, di, bb4.w), 0.0f);
    }
    __syncwarp(hmask);

    if (active) {
        float s = 0.0f;
#pragma unroll 8
        for (int k = 0; k < 64; k++)
            s = fmaf(x1s[nidx][k], w2s[k][c], s);
        g_h2[(size_t)node * 16 + c] = s;
    }
}

// ------- agg2: out = A_hat h2 + b2 (2 nodes/warp, coalesced w cache) -------
__global__ __launch_bounds__(256) void agg2_kernel(const float* __restrict__ b2,
                                                   float* __restrict__ dout) {
    __shared__ int2 est[8][2][16];
    int tid  = threadIdx.x;
    int wy   = tid >> 5;
    int lane = tid & 31;
    int half = lane >> 4;
    int c    = lane & 15;
    unsigned hmask = half ? 0xFFFF0000u : 0x0000FFFFu;
    int node = blockIdx.x * 16 + wy * 2 + half;
    if (node >= N_NODES) return;

    int cnt = g_degi[node];
    int cnt32 = min(cnt, CAP);
    float di = g_dinv[node];
    const float* h2 = g_h2;
    float acc = *h2_row(h2, node, c) * di;
    const int* slotp = g_slot + (size_t)node * CAP;
    const float* wslotp = g_wslot + (size_t)node * CAP;

    for (int bb = 0; bb < cnt32; bb += 16) {
        if (bb + c < cnt32) {
            // both loads coalesced (16 consecutive words)
            est[wy][half][c] = make_int2(slotp[bb + c],
                                         __float_as_int(wslotp[bb + c]));
        }
        __syncwarp(hmask);
        int m = min(cnt32 - bb, 16);
        for (int j = 0; j < m; j++) {
            int2 e = est[wy][half][j];           // LDS.64 broadcast
            float w = __int_as_float(e.y);
            acc = fmaf(*h2_row(h2, e.x, c), w, acc);
        }
        __syncwarp(hmask);
    }
    if (cnt > CAP) {                              // overflow (expected: never)
        int no = min(g_ovf_cnt, OVF_CAP);
        for (int o = 0; o < no; o++) {
            int2 ev = g_ovf[o];
            if (ev.x == node) {
                float w = __ldg(&g_dinv[ev.y]);
                acc = fmaf(*h2_row(h2, ev.y, c), w, acc);
            }
        }
    }
    dout[(size_t)node * 16 + c] = fmaf(acc, di, b2[c]);
}

// ---------------- launch --------------------------------------------------
extern "C" void kernel_launch(void* const* d_in, const int* in_sizes, int n_in,
                              void* d_out, int out_size) {
    const float* X  = (const float*)d_in[0];
    const void*  EI = (const void*)d_in[1];
    const float* W1 = (const float*)d_in[2];
    const float* b1 = (const float*)d_in[3];
    const float* W2 = (const float*)d_in[4];
    const float* b2 = (const float*)d_in[5];
    float* dout = (float*)d_out;
    (void)in_sizes; (void)n_in; (void)out_size;

    const int T = 256;
    bool fork = (g_s2 != nullptr && g_ev_fork != nullptr && g_ev_join != nullptr);

    if (fork) {
        cudaEventRecord(g_ev_fork, 0);
        cudaStreamWaitEvent(g_s2, g_ev_fork, 0);
        gemm1_kernel<<<(N_NODES + 63) / 64, 256, 0, g_s2>>>(X, W1);
        cudaEventRecord(g_ev_join, g_s2);
    }

    zero_detect_kernel<<<(N_NODES + T - 1) / T, T>>>((const int*)EI);
    slot_scatter_kernel<<<(N_EDGES + T - 1) / T, T>>>(EI);
    dinv_kernel<<<(N_NODES + T - 1) / T, T>>>();

    if (fork) {
        cudaStreamWaitEvent(0, g_ev_join, 0);
    } else {
        gemm1_kernel<<<(N_NODES + 63) / 64, 256>>>(X, W1);
    }

    agg1_gemm2_kernel<<<(N_NODES + 15) / 16, 256>>>(b1, W2);
    agg2_kernel<<<(N_NODES + 15) / 16, 256>>>(b2, dout);
}